// round 13
// baseline (speedup 1.0000x reference)
#include <cuda_runtime.h>
#include <math.h>

#define Bb 8
#define Nn 16384
#define Dd 768
#define Rr 3
#define NE 4

// ---------------- device scratch ----------------
__device__ float g_feat[Bb * Rr * Nn];      // xr planar [b][r][h*128+w]
__device__ float g_part[4096 * Rr];         // per-block partials (512 per b)
__device__ float4 g_mixed4[Bb * Nn];        // interleaved (m0,m1,m2,unused)

__device__ __forceinline__ void pdl_wait() {
    asm volatile("griddepcontrol.wait;" ::: "memory");
}

// ---------------- kernel 1: xr = x@Wd + bd (planar) + partial sums ----------------
// 4096 blocks x 256 threads; each warp handles 4 consecutive rows.
__global__ void k1_proj_down(const float* __restrict__ x,
                             const float* __restrict__ Wd,
                             const float* __restrict__ bd) {
    __shared__ float sw0[Dd], sw1[Dd], sw2[Dd];
    __shared__ float wsum[32][3];
    int tid = threadIdx.x;
    for (int i = tid; i < Dd; i += 256) {
        sw0[i] = Wd[i * 3 + 0];
        sw1[i] = Wd[i * 3 + 1];
        sw2[i] = Wd[i * 3 + 2];
    }
    __syncthreads();

    int warp = tid >> 5, lane = tid & 31;
    long row0 = ((long)blockIdx.x * 8 + warp) * 4;
    const float4* xp = (const float4*)(x + row0 * Dd);  // row stride 192 float4

    float a00 = 0.f, a01 = 0.f, a02 = 0.f;
    float a10 = 0.f, a11 = 0.f, a12 = 0.f;
    float a20 = 0.f, a21 = 0.f, a22 = 0.f;
    float a30 = 0.f, a31 = 0.f, a32 = 0.f;
#pragma unroll
    for (int c = 0; c < 6; c++) {
        int d4 = c * 32 + lane;
        float4 w0 = *(const float4*)(sw0 + d4 * 4);
        float4 w1 = *(const float4*)(sw1 + d4 * 4);
        float4 w2 = *(const float4*)(sw2 + d4 * 4);
        float4 x0 = __ldg(xp + 0 * 192 + d4);
        float4 x1 = __ldg(xp + 1 * 192 + d4);
        float4 x2 = __ldg(xp + 2 * 192 + d4);
        float4 x3 = __ldg(xp + 3 * 192 + d4);
        a00 = fmaf(x0.x, w0.x, fmaf(x0.y, w0.y, fmaf(x0.z, w0.z, fmaf(x0.w, w0.w, a00))));
        a01 = fmaf(x0.x, w1.x, fmaf(x0.y, w1.y, fmaf(x0.z, w1.z, fmaf(x0.w, w1.w, a01))));
        a02 = fmaf(x0.x, w2.x, fmaf(x0.y, w2.y, fmaf(x0.z, w2.z, fmaf(x0.w, w2.w, a02))));
        a10 = fmaf(x1.x, w0.x, fmaf(x1.y, w0.y, fmaf(x1.z, w0.z, fmaf(x1.w, w0.w, a10))));
        a11 = fmaf(x1.x, w1.x, fmaf(x1.y, w1.y, fmaf(x1.z, w1.z, fmaf(x1.w, w1.w, a11))));
        a12 = fmaf(x1.x, w2.x, fmaf(x1.y, w2.y, fmaf(x1.z, w2.z, fmaf(x1.w, w2.w, a12))));
        a20 = fmaf(x2.x, w0.x, fmaf(x2.y, w0.y, fmaf(x2.z, w0.z, fmaf(x2.w, w0.w, a20))));
        a21 = fmaf(x2.x, w1.x, fmaf(x2.y, w1.y, fmaf(x2.z, w1.z, fmaf(x2.w, w1.w, a21))));
        a22 = fmaf(x2.x, w2.x, fmaf(x2.y, w2.y, fmaf(x2.z, w2.z, fmaf(x2.w, w2.w, a22))));
        a30 = fmaf(x3.x, w0.x, fmaf(x3.y, w0.y, fmaf(x3.z, w0.z, fmaf(x3.w, w0.w, a30))));
        a31 = fmaf(x3.x, w1.x, fmaf(x3.y, w1.y, fmaf(x3.z, w1.z, fmaf(x3.w, w1.w, a31))));
        a32 = fmaf(x3.x, w2.x, fmaf(x3.y, w2.y, fmaf(x3.z, w2.z, fmaf(x3.w, w2.w, a32))));
    }
#pragma unroll
    for (int off = 16; off > 0; off >>= 1) {
        a00 += __shfl_xor_sync(0xFFFFFFFFu, a00, off);
        a01 += __shfl_xor_sync(0xFFFFFFFFu, a01, off);
        a02 += __shfl_xor_sync(0xFFFFFFFFu, a02, off);
        a10 += __shfl_xor_sync(0xFFFFFFFFu, a10, off);
        a11 += __shfl_xor_sync(0xFFFFFFFFu, a11, off);
        a12 += __shfl_xor_sync(0xFFFFFFFFu, a12, off);
        a20 += __shfl_xor_sync(0xFFFFFFFFu, a20, off);
        a21 += __shfl_xor_sync(0xFFFFFFFFu, a21, off);
        a22 += __shfl_xor_sync(0xFFFFFFFFu, a22, off);
        a30 += __shfl_xor_sync(0xFFFFFFFFu, a30, off);
        a31 += __shfl_xor_sync(0xFFFFFFFFu, a31, off);
        a32 += __shfl_xor_sync(0xFFFFFFFFu, a32, off);
    }
    if (lane == 0) {
        float b0 = bd[0], b1 = bd[1], b2 = bd[2];
        int w4 = warp * 4;
        wsum[w4 + 0][0] = a00 + b0; wsum[w4 + 0][1] = a01 + b1; wsum[w4 + 0][2] = a02 + b2;
        wsum[w4 + 1][0] = a10 + b0; wsum[w4 + 1][1] = a11 + b1; wsum[w4 + 1][2] = a12 + b2;
        wsum[w4 + 2][0] = a20 + b0; wsum[w4 + 2][1] = a21 + b1; wsum[w4 + 2][2] = a22 + b2;
        wsum[w4 + 3][0] = a30 + b0; wsum[w4 + 3][1] = a31 + b1; wsum[w4 + 3][2] = a32 + b2;
    }
    __syncthreads();

    int b = blockIdx.x >> 9;               // 512 blocks per batch
    int nbase = (blockIdx.x & 511) * 32;
    if (tid < 96) {
        int r = tid >> 5, n = tid & 31;
        g_feat[((b * Rr + r) * Nn) + nbase + n] = wsum[n][r];
    }
    if (tid < 3) {
        float acc = 0.f;
#pragma unroll
        for (int n = 0; n < 32; n++) acc += wsum[n][tid];
        g_part[blockIdx.x * Rr + tid] = acc;
    }
}

// ---------------- fused middle: gating + pyramid + conv + mix ----------------
__device__ __forceinline__ float conv3x3s(const float* src, int S,
                                          int oi, int oj,
                                          const float* k9, float bias) {
    float acc = bias;
#pragma unroll
    for (int di = 0; di < 3; di++) {
        int y = oi + di - 1;
        if ((unsigned)y >= (unsigned)S) continue;
#pragma unroll
        for (int dj = 0; dj < 3; dj++) {
            int xx = oj + dj - 1;
            if ((unsigned)xx >= (unsigned)S) continue;
            acc = fmaf(src[y * S + xx], k9[di * 3 + dj], acc);
        }
    }
    return acc;
}

__device__ __forceinline__ float up_sample_s(const float* src, int S,
                                             int h, int w, float ratio) {
    float sy = (h + 0.5f) * ratio - 0.5f;
    float sx = (w + 0.5f) * ratio - 0.5f;
    float fy = floorf(sy), fx = floorf(sx);
    float wy = sy - fy, wx = sx - fx;
    int y0 = (int)fy, x0 = (int)fx;
    int ya = max(y0, 0), yb = min(y0 + 1, S - 1);
    int xa = max(x0, 0), xb = min(x0 + 1, S - 1);
    float v00 = src[ya * S + xa], v01 = src[ya * S + xb];
    float v10 = src[yb * S + xa], v11 = src[yb * S + xb];
    float top = v00 + wx * (v01 - v00);
    float bot = v10 + wx * (v11 - v10);
    return top + wy * (bot - top);
}

// 96 blocks (4 row-strips of 32 per (b,r) plane) x 1024 threads; smem ~106KB.
__global__ void k3_fused(const float* __restrict__ noise,
                         const float* __restrict__ Wg,
                         const float* __restrict__ Wn,
                         const float* __restrict__ dwk,
                         const float* __restrict__ dwb) {
    extern __shared__ float sm[];
    float* sA  = sm;            // 16384 (window-filled)
    float* sD1 = sA + 16384;    // 4096
    float* sC1 = sD1 + 4096;    // 4096
    float* sD2 = sC1 + 4096;    // 1024
    float* sC2 = sD2 + 1024;    // 1024
    float* sD3 = sC2 + 1024;    // 256
    float* sC3 = sD3 + 256;     // 256
    __shared__ float sxa[3];
    __shared__ float sG[NE];

    int ch = blockIdx.x >> 2;
    int strip = blockIdx.x & 3;
    int h0 = strip * 32;
    int b = ch / 3, r = ch % 3;
    int t = threadIdx.x;

    // prologue independent of k1 (runs before wait under PDL)
    float k9[9];
#pragma unroll
    for (int j = 0; j < 9; j++) k9[j] = __ldg(dwk + r * 9 + j);
    float bias = __ldg(dwb + r);

    int alo = max(h0 - 13, 0), ahi = min(h0 + 44, 127);
    int d1lo = max(h0 / 2 - 2, 0), d1hi = min(h0 / 2 + 17, 63);
    int c1lo = max(h0 / 2 - 1, 0), c1hi = min(h0 / 2 + 16, 63);
    int d2lo = max(h0 / 4 - 2, 0), d2hi = min(h0 / 4 + 9, 31);
    int c2lo = max(h0 / 4 - 1, 0), c2hi = min(h0 / 4 + 8, 31);
    int d3lo = max(h0 / 8 - 2, 0), d3hi = min(h0 / 8 + 5, 15);
    int c3lo = max(h0 / 8 - 1, 0), c3hi = min(h0 / 8 + 4, 15);

    pdl_wait();   // k1's g_feat / g_part now visible

    {
        const float4* src = (const float4*)(g_feat + ch * Nn);
        float4* dst = (float4*)sA;
        int cnt4 = (ahi - alo + 1) * 32;
        int base4 = alo * 32;
        for (int i = t; i < cnt4; i += 1024) dst[base4 + i] = __ldg(src + base4 + i);
    }

    if (t < 96) {
        int warp = t >> 5, lane = t & 31;
        float s0 = 0.f, s1 = 0.f, s2 = 0.f, s3 = 0.f;
        const float* pp = g_part + b * 512 * Rr + warp;
#pragma unroll
        for (int i = 0; i < 4; i++) {
            s0 += __ldg(pp + (lane + (i * 4 + 0) * 32) * Rr);
            s1 += __ldg(pp + (lane + (i * 4 + 1) * 32) * Rr);
            s2 += __ldg(pp + (lane + (i * 4 + 2) * 32) * Rr);
            s3 += __ldg(pp + (lane + (i * 4 + 3) * 32) * Rr);
        }
        float s = (s0 + s1) + (s2 + s3);
#pragma unroll
        for (int off = 16; off > 0; off >>= 1)
            s += __shfl_xor_sync(0xFFFFFFFFu, s, off);
        if (lane == 0) sxa[warp] = s * (1.0f / (float)Nn);
    }
    __syncthreads();

    if (t == 0) {
        float xa0 = sxa[0], xa1 = sxa[1], xa2 = sxa[2];
        float Hlog[NE];
#pragma unroll
        for (int e = 0; e < NE; e++) {
            float hg = xa0 * Wg[0 * NE + e] + xa1 * Wg[1 * NE + e] + xa2 * Wg[2 * NE + e];
            float hn = xa0 * Wn[0 * NE + e] + xa1 * Wn[1 * NE + e] + xa2 * Wn[2 * NE + e];
            float sp = fmaxf(hn, 0.f) + log1pf(expf(-fabsf(hn)));
            Hlog[e] = hg + noise[b * NE + e] * sp;
        }
        int i1 = 0;
#pragma unroll
        for (int e = 1; e < NE; e++) if (Hlog[e] > Hlog[i1]) i1 = e;
        int i2 = -1;
#pragma unroll
        for (int e = 0; e < NE; e++) {
            if (e == i1) continue;
            if (i2 < 0 || Hlog[e] > Hlog[i2]) i2 = e;
        }
        float e2 = expf(Hlog[i2] - Hlog[i1]);
        float invZ = 1.0f / (1.0f + e2);
#pragma unroll
        for (int e = 0; e < NE; e++)
            sG[e] = (e == i1) ? invZ : ((e == i2) ? e2 * invZ : 0.0f);
    }

    __syncthreads();  // sA window + gating ready

    float G0 = sG[0], G1 = sG[1], G2 = sG[2], G3 = sG[3];

    if (G1 != 0.f) {
        int cnt = (d1hi - d1lo + 1) * 64;
        for (int i = t; i < cnt; i += 1024) {
            int rr = d1lo + (i >> 6), oj = i & 63;
            int y0 = 2 * rr, x0 = 2 * oj;
            sD1[rr * 64 + oj] = 0.25f * (sA[y0 * 128 + x0] + sA[y0 * 128 + x0 + 1] +
                                         sA[(y0 + 1) * 128 + x0] + sA[(y0 + 1) * 128 + x0 + 1]);
        }
    }
    if (G2 != 0.f) {
        int cnt = (d2hi - d2lo + 1) * 32;
        if (t < cnt) {
            int rr = d2lo + (t >> 5), oj = t & 31;
            int y0 = 4 * rr + 1, x0 = 4 * oj + 1;
            sD2[rr * 32 + oj] = 0.25f * (sA[y0 * 128 + x0] + sA[y0 * 128 + x0 + 1] +
                                         sA[(y0 + 1) * 128 + x0] + sA[(y0 + 1) * 128 + x0 + 1]);
        }
    }
    if (G3 != 0.f) {
        int cnt = (d3hi - d3lo + 1) * 16;
        if (t < cnt) {
            int rr = d3lo + (t >> 4), oj = t & 15;
            int y0 = 8 * rr + 3, x0 = 8 * oj + 3;
            sD3[rr * 16 + oj] = 0.25f * (sA[y0 * 128 + x0] + sA[y0 * 128 + x0 + 1] +
                                         sA[(y0 + 1) * 128 + x0] + sA[(y0 + 1) * 128 + x0 + 1]);
        }
    }

    float c0r[4] = {0.f, 0.f, 0.f, 0.f};
    if (G0 != 0.f) {
#pragma unroll
        for (int k = 0; k < 4; k++) {
            int p = k * 1024 + t;
            c0r[k] = conv3x3s(sA, 128, h0 + (p >> 7), p & 127, k9, bias);
        }
    }

    __syncthreads();  // sD* windows complete

    if (G1 != 0.f) {
        int cnt = (c1hi - c1lo + 1) * 64;
        for (int i = t; i < cnt; i += 1024) {
            int rr = c1lo + (i >> 6), oj = i & 63;
            sC1[rr * 64 + oj] = conv3x3s(sD1, 64, rr, oj, k9, bias);
        }
    }
    if (G2 != 0.f) {
        int cnt = (c2hi - c2lo + 1) * 32;
        if (t < cnt) {
            int rr = c2lo + (t >> 5), oj = t & 31;
            sC2[rr * 32 + oj] = conv3x3s(sD2, 32, rr, oj, k9, bias);
        }
    }
    if (G3 != 0.f) {
        int cnt = (c3hi - c3lo + 1) * 16;
        if (t < cnt) {
            int rr = c3lo + (t >> 4), oj = t & 15;
            sC3[rr * 16 + oj] = conv3x3s(sD3, 16, rr, oj, k9, bias);
        }
    }

    __syncthreads();  // sC* windows complete

    float* gm = (float*)g_mixed4;
#pragma unroll
    for (int k = 0; k < 4; k++) {
        int p = k * 1024 + t;
        int h = h0 + (p >> 7), w = p & 127;
        float acc = G0 * c0r[k];
        if (G1 != 0.f) acc += G1 * up_sample_s(sC1, 64, h, w, 0.5f);
        if (G2 != 0.f) acc += G2 * up_sample_s(sC2, 32, h, w, 0.25f);
        if (G3 != 0.f) acc += G3 * up_sample_s(sC3, 16, h, w, 0.125f);
        gm[(b * Nn + h * 128 + w) * 4 + r] = acc;
    }
}

// ---------------- kernel 4: out = x + mixed @ Wu + bu ----------------
// 16384 blocks x 384 threads; REVERSED block->row order so the first waves
// read the x rows k1 streamed last (L2 hot tail). out stored with __stcs to
// avoid evicting those lines. Per 16B of stream: 2 LDG.128 + 1 STG.128.
__global__ void k4_out(const float* __restrict__ x,
                       const float* __restrict__ Wu,
                       const float* __restrict__ bu,
                       float* __restrict__ out) {
    int t = threadIdx.x;
    int sub = t / 192;          // 0..1
    int d4 = t - sub * 192;     // float4 column 0..191

    float4 w0 = __ldg((const float4*)Wu + 0 * 192 + d4);
    float4 w1 = __ldg((const float4*)Wu + 1 * 192 + d4);
    float4 w2 = __ldg((const float4*)Wu + 2 * 192 + d4);
    float4 bb = __ldg((const float4*)bu + d4);

    long rbase = (long)(16383 - blockIdx.x) * 8;   // reversed order
    const float4* xp = (const float4*)x;
    float4* op = (float4*)out;

    pdl_wait();   // k3's g_mixed4 now visible

#pragma unroll
    for (int i = 0; i < 4; i++) {
        long row = rbase + i * 2 + sub;
        float4 m = __ldg(g_mixed4 + row);   // (m0,m1,m2,·)
        long idx = row * 192 + d4;
        float4 xv = __ldg(xp + idx);
        float4 o;
        o.x = xv.x + fmaf(m.x, w0.x, fmaf(m.y, w1.x, fmaf(m.z, w2.x, bb.x)));
        o.y = xv.y + fmaf(m.x, w0.y, fmaf(m.y, w1.y, fmaf(m.z, w2.y, bb.y)));
        o.z = xv.z + fmaf(m.x, w0.z, fmaf(m.y, w1.z, fmaf(m.z, w2.z, bb.z)));
        o.w = xv.w + fmaf(m.x, w0.w, fmaf(m.y, w1.w, fmaf(m.z, w2.w, bb.w)));
        __stcs(op + idx, o);
    }
}

// ---------------- launcher ----------------
extern "C" void kernel_launch(void* const* d_in, const int* in_sizes, int n_in,
                              void* d_out, int out_size) {
    const float* x     = (const float*)d_in[0];
    const float* noise = (const float*)d_in[1];
    const float* Wd    = (const float*)d_in[2];
    const float* bd    = (const float*)d_in[3];
    const float* Wu    = (const float*)d_in[4];
    const float* bu    = (const float*)d_in[5];
    const float* Wg    = (const float*)d_in[6];
    const float* Wn    = (const float*)d_in[7];
    const float* dwk   = (const float*)d_in[8];
    const float* dwb   = (const float*)d_in[9];
    float* out = (float*)d_out;

    const int SMEM3 = (16384 + 4096 * 2 + 1024 * 2 + 256 * 2) * 4;
    cudaFuncSetAttribute(k3_fused, cudaFuncAttributeMaxDynamicSharedMemorySize, SMEM3);

    cudaLaunchAttribute pdl[1];
    pdl[0].id = cudaLaunchAttributeProgrammaticStreamSerialization;
    pdl[0].val.programmaticStreamSerializationAllowed = 1;

    {
        cudaLaunchConfig_t cfg = {};
        cfg.gridDim = dim3(4096);
        cfg.blockDim = dim3(256);
        cfg.stream = 0;
        cfg.attrs = pdl;
        cfg.numAttrs = 1;
        cudaLaunchKernelEx(&cfg, k1_proj_down, x, Wd, bd);
    }
    {
        cudaLaunchConfig_t cfg = {};
        cfg.gridDim = dim3(96);
        cfg.blockDim = dim3(1024);
        cfg.dynamicSmemBytes = SMEM3;
        cfg.stream = 0;
        cfg.attrs = pdl;
        cfg.numAttrs = 1;
        cudaLaunchKernelEx(&cfg, k3_fused, noise, Wg, Wn, dwk, dwb);
    }
    {
        cudaLaunchConfig_t cfg = {};
        cfg.gridDim = dim3(16384);
        cfg.blockDim = dim3(384);
        cfg.stream = 0;
        cfg.attrs = pdl;
        cfg.numAttrs = 1;
        cudaLaunchKernelEx(&cfg, k4_out, x, Wu, bu, out);
    }
}

// round 14
// speedup vs baseline: 1.0721x; 1.0721x over previous
#include <cuda_runtime.h>
#include <math.h>

#define Bb 8
#define Nn 16384
#define Dd 768
#define Rr 3
#define NE 4

// ---------------- device scratch ----------------
__device__ float g_feat[Bb * Rr * Nn];      // xr planar [b][r][h*128+w]
__device__ float g_part[4096 * Rr];         // per-block partials (512 per b)
__device__ float4 g_mixed4[Bb * Nn];        // interleaved (m0,m1,m2,unused)

__device__ __forceinline__ void pdl_wait() {
    asm volatile("griddepcontrol.wait;" ::: "memory");
}

// ---------------- kernel 1: xr = x@Wd + bd (planar) + partial sums ----------------
// 4096 blocks x 256 threads; each warp handles 4 consecutive rows.
__global__ void k1_proj_down(const float* __restrict__ x,
                             const float* __restrict__ Wd,
                             const float* __restrict__ bd) {
    __shared__ float sw0[Dd], sw1[Dd], sw2[Dd];
    __shared__ float wsum[32][3];
    int tid = threadIdx.x;
    for (int i = tid; i < Dd; i += 256) {
        sw0[i] = Wd[i * 3 + 0];
        sw1[i] = Wd[i * 3 + 1];
        sw2[i] = Wd[i * 3 + 2];
    }
    __syncthreads();

    int warp = tid >> 5, lane = tid & 31;
    long row0 = ((long)blockIdx.x * 8 + warp) * 4;
    const float4* xp = (const float4*)(x + row0 * Dd);  // row stride 192 float4

    float a00 = 0.f, a01 = 0.f, a02 = 0.f;
    float a10 = 0.f, a11 = 0.f, a12 = 0.f;
    float a20 = 0.f, a21 = 0.f, a22 = 0.f;
    float a30 = 0.f, a31 = 0.f, a32 = 0.f;
#pragma unroll
    for (int c = 0; c < 6; c++) {
        int d4 = c * 32 + lane;
        float4 w0 = *(const float4*)(sw0 + d4 * 4);
        float4 w1 = *(const float4*)(sw1 + d4 * 4);
        float4 w2 = *(const float4*)(sw2 + d4 * 4);
        float4 x0 = __ldg(xp + 0 * 192 + d4);
        float4 x1 = __ldg(xp + 1 * 192 + d4);
        float4 x2 = __ldg(xp + 2 * 192 + d4);
        float4 x3 = __ldg(xp + 3 * 192 + d4);
        a00 = fmaf(x0.x, w0.x, fmaf(x0.y, w0.y, fmaf(x0.z, w0.z, fmaf(x0.w, w0.w, a00))));
        a01 = fmaf(x0.x, w1.x, fmaf(x0.y, w1.y, fmaf(x0.z, w1.z, fmaf(x0.w, w1.w, a01))));
        a02 = fmaf(x0.x, w2.x, fmaf(x0.y, w2.y, fmaf(x0.z, w2.z, fmaf(x0.w, w2.w, a02))));
        a10 = fmaf(x1.x, w0.x, fmaf(x1.y, w0.y, fmaf(x1.z, w0.z, fmaf(x1.w, w0.w, a10))));
        a11 = fmaf(x1.x, w1.x, fmaf(x1.y, w1.y, fmaf(x1.z, w1.z, fmaf(x1.w, w1.w, a11))));
        a12 = fmaf(x1.x, w2.x, fmaf(x1.y, w2.y, fmaf(x1.z, w2.z, fmaf(x1.w, w2.w, a12))));
        a20 = fmaf(x2.x, w0.x, fmaf(x2.y, w0.y, fmaf(x2.z, w0.z, fmaf(x2.w, w0.w, a20))));
        a21 = fmaf(x2.x, w1.x, fmaf(x2.y, w1.y, fmaf(x2.z, w1.z, fmaf(x2.w, w1.w, a21))));
        a22 = fmaf(x2.x, w2.x, fmaf(x2.y, w2.y, fmaf(x2.z, w2.z, fmaf(x2.w, w2.w, a22))));
        a30 = fmaf(x3.x, w0.x, fmaf(x3.y, w0.y, fmaf(x3.z, w0.z, fmaf(x3.w, w0.w, a30))));
        a31 = fmaf(x3.x, w1.x, fmaf(x3.y, w1.y, fmaf(x3.z, w1.z, fmaf(x3.w, w1.w, a31))));
        a32 = fmaf(x3.x, w2.x, fmaf(x3.y, w2.y, fmaf(x3.z, w2.z, fmaf(x3.w, w2.w, a32))));
    }
#pragma unroll
    for (int off = 16; off > 0; off >>= 1) {
        a00 += __shfl_xor_sync(0xFFFFFFFFu, a00, off);
        a01 += __shfl_xor_sync(0xFFFFFFFFu, a01, off);
        a02 += __shfl_xor_sync(0xFFFFFFFFu, a02, off);
        a10 += __shfl_xor_sync(0xFFFFFFFFu, a10, off);
        a11 += __shfl_xor_sync(0xFFFFFFFFu, a11, off);
        a12 += __shfl_xor_sync(0xFFFFFFFFu, a12, off);
        a20 += __shfl_xor_sync(0xFFFFFFFFu, a20, off);
        a21 += __shfl_xor_sync(0xFFFFFFFFu, a21, off);
        a22 += __shfl_xor_sync(0xFFFFFFFFu, a22, off);
        a30 += __shfl_xor_sync(0xFFFFFFFFu, a30, off);
        a31 += __shfl_xor_sync(0xFFFFFFFFu, a31, off);
        a32 += __shfl_xor_sync(0xFFFFFFFFu, a32, off);
    }
    if (lane == 0) {
        float b0 = bd[0], b1 = bd[1], b2 = bd[2];
        int w4 = warp * 4;
        wsum[w4 + 0][0] = a00 + b0; wsum[w4 + 0][1] = a01 + b1; wsum[w4 + 0][2] = a02 + b2;
        wsum[w4 + 1][0] = a10 + b0; wsum[w4 + 1][1] = a11 + b1; wsum[w4 + 1][2] = a12 + b2;
        wsum[w4 + 2][0] = a20 + b0; wsum[w4 + 2][1] = a21 + b1; wsum[w4 + 2][2] = a22 + b2;
        wsum[w4 + 3][0] = a30 + b0; wsum[w4 + 3][1] = a31 + b1; wsum[w4 + 3][2] = a32 + b2;
    }
    __syncthreads();

    int b = blockIdx.x >> 9;               // 512 blocks per batch
    int nbase = (blockIdx.x & 511) * 32;
    if (tid < 96) {
        int r = tid >> 5, n = tid & 31;
        g_feat[((b * Rr + r) * Nn) + nbase + n] = wsum[n][r];
    }
    if (tid < 3) {
        float acc = 0.f;
#pragma unroll
        for (int n = 0; n < 32; n++) acc += wsum[n][tid];
        g_part[blockIdx.x * Rr + tid] = acc;
    }
}

// ---------------- fused middle helpers ----------------
// bilinear upsample with row-windowed source (relative indexing)
__device__ __forceinline__ float up_rel(const float* src, int S, int rowlo,
                                        int h, int w, float ratio) {
    float sy = (h + 0.5f) * ratio - 0.5f;
    float sx = (w + 0.5f) * ratio - 0.5f;
    float fy = floorf(sy), fx = floorf(sx);
    float wy = sy - fy, wx = sx - fx;
    int y0 = (int)fy, x0 = (int)fx;
    int ya = max(y0, 0) - rowlo, yb = min(y0 + 1, S - 1) - rowlo;
    int xa = max(x0, 0), xb = min(x0 + 1, S - 1);
    float v00 = src[ya * S + xa], v01 = src[ya * S + xb];
    float v10 = src[yb * S + xa], v11 = src[yb * S + xb];
    float top = v00 + wx * (v01 - v00);
    float bot = v10 + wx * (v11 - v10);
    return top + wy * (bot - top);
}

// 3x3 conv with absolute bounds checks, row-windowed source
__device__ __forceinline__ float conv_rel(const float* src, int S, int rowlo,
                                          int oi, int oj,
                                          const float* k9, float bias) {
    float acc = bias;
#pragma unroll
    for (int di = 0; di < 3; di++) {
        int y = oi + di - 1;
        if ((unsigned)y >= (unsigned)S) continue;
#pragma unroll
        for (int dj = 0; dj < 3; dj++) {
            int xx = oj + dj - 1;
            if ((unsigned)xx >= (unsigned)S) continue;
            acc = fmaf(src[(y - rowlo) * S + xx], k9[di * 3 + dj], acc);
        }
    }
    return acc;
}

// 192 blocks (8 row-strips of 16 per (b,r) plane) x 1024 threads; smem ~29.6KB
// -> 2 blocks/SM, single wave. All levels computed only in needed row windows.
__global__ void __launch_bounds__(1024, 2)
k3_fused(const float* __restrict__ noise,
         const float* __restrict__ Wg,
         const float* __restrict__ Wn,
         const float* __restrict__ dwk,
         const float* __restrict__ dwb) {
    extern __shared__ float sm[];
    float* sA  = sm;                 // 42*128 = 5376 (rows [alo,ahi])
    float* sD1 = sA + 5376;          // 12*64
    float* sC1 = sD1 + 768;          // 10*64
    float* sD2 = sC1 + 640;          // 8*32
    float* sC2 = sD2 + 256;          // 6*32
    float* sD3 = sC2 + 192;          // 6*16
    float* sC3 = sD3 + 96;           // 4*16
    __shared__ float sxa[3];
    __shared__ float sG[NE];

    int ch = blockIdx.x >> 3;
    int strip = blockIdx.x & 7;
    int h0 = strip * 16;
    int b = ch / 3, r = ch % 3;
    int t = threadIdx.x;

    // prologue independent of k1 (runs before wait under PDL)
    float k9[9];
#pragma unroll
    for (int j = 0; j < 9; j++) k9[j] = __ldg(dwk + r * 9 + j);
    float bias = __ldg(dwb + r);

    // row windows for a 16-row strip (verified incl. edge clamps)
    int alo = max(h0 - 13, 0), ahi = min(h0 + 28, 127);
    int d1lo = max(h0 / 2 - 2, 0), d1hi = min(h0 / 2 + 9, 63);
    int c1lo = max(h0 / 2 - 1, 0), c1hi = min(h0 / 2 + 8, 63);
    int d2lo = max(h0 / 4 - 2, 0), d2hi = min(h0 / 4 + 5, 31);
    int c2lo = max(h0 / 4 - 1, 0), c2hi = min(h0 / 4 + 4, 31);
    int d3lo = max(h0 / 8 - 2, 0), d3hi = min(h0 / 8 + 3, 15);
    int c3lo = max(h0 / 8 - 1, 0), c3hi = min(h0 / 8 + 2, 15);

    pdl_wait();   // k1's g_feat / g_part now visible

    // windowed sA load (relative rows)
    {
        const float4* src = (const float4*)(g_feat + ch * Nn) + alo * 32;
        float4* dst = (float4*)sA;
        int cnt4 = (ahi - alo + 1) * 32;
        for (int i = t; i < cnt4; i += 1024) dst[i] = __ldg(src + i);
    }

    if (t < 96) {
        int warp = t >> 5, lane = t & 31;
        float s0 = 0.f, s1 = 0.f, s2 = 0.f, s3 = 0.f;
        const float* pp = g_part + b * 512 * Rr + warp;
#pragma unroll
        for (int i = 0; i < 4; i++) {
            s0 += __ldg(pp + (lane + (i * 4 + 0) * 32) * Rr);
            s1 += __ldg(pp + (lane + (i * 4 + 1) * 32) * Rr);
            s2 += __ldg(pp + (lane + (i * 4 + 2) * 32) * Rr);
            s3 += __ldg(pp + (lane + (i * 4 + 3) * 32) * Rr);
        }
        float s = (s0 + s1) + (s2 + s3);
#pragma unroll
        for (int off = 16; off > 0; off >>= 1)
            s += __shfl_xor_sync(0xFFFFFFFFu, s, off);
        if (lane == 0) sxa[warp] = s * (1.0f / (float)Nn);
    }
    __syncthreads();

    if (t == 0) {
        float xa0 = sxa[0], xa1 = sxa[1], xa2 = sxa[2];
        float Hlog[NE];
#pragma unroll
        for (int e = 0; e < NE; e++) {
            float hg = xa0 * Wg[0 * NE + e] + xa1 * Wg[1 * NE + e] + xa2 * Wg[2 * NE + e];
            float hn = xa0 * Wn[0 * NE + e] + xa1 * Wn[1 * NE + e] + xa2 * Wn[2 * NE + e];
            float sp = fmaxf(hn, 0.f) + log1pf(expf(-fabsf(hn)));
            Hlog[e] = hg + noise[b * NE + e] * sp;
        }
        int i1 = 0;
#pragma unroll
        for (int e = 1; e < NE; e++) if (Hlog[e] > Hlog[i1]) i1 = e;
        int i2 = -1;
#pragma unroll
        for (int e = 0; e < NE; e++) {
            if (e == i1) continue;
            if (i2 < 0 || Hlog[e] > Hlog[i2]) i2 = e;
        }
        float e2 = expf(Hlog[i2] - Hlog[i1]);
        float invZ = 1.0f / (1.0f + e2);
#pragma unroll
        for (int e = 0; e < NE; e++)
            sG[e] = (e == i1) ? invZ : ((e == i2) ? e2 * invZ : 0.0f);
    }

    __syncthreads();  // sA window + gating ready

    float G0 = sG[0], G1 = sG[1], G2 = sG[2], G3 = sG[3];

    // windowed downsamples — only for experts with nonzero gate
    if (G1 != 0.f) {
        int cnt = (d1hi - d1lo + 1) * 64;
        for (int i = t; i < cnt; i += 1024) {
            int rr = d1lo + (i >> 6), oj = i & 63;
            int y0 = 2 * rr - alo, x0 = 2 * oj;
            sD1[(rr - d1lo) * 64 + oj] =
                0.25f * (sA[y0 * 128 + x0] + sA[y0 * 128 + x0 + 1] +
                         sA[(y0 + 1) * 128 + x0] + sA[(y0 + 1) * 128 + x0 + 1]);
        }
    }
    if (G2 != 0.f) {
        int cnt = (d2hi - d2lo + 1) * 32;
        if (t < cnt) {
            int rr = d2lo + (t >> 5), oj = t & 31;
            int y0 = 4 * rr + 1 - alo, x0 = 4 * oj + 1;
            sD2[(rr - d2lo) * 32 + oj] =
                0.25f * (sA[y0 * 128 + x0] + sA[y0 * 128 + x0 + 1] +
                         sA[(y0 + 1) * 128 + x0] + sA[(y0 + 1) * 128 + x0 + 1]);
        }
    }
    if (G3 != 0.f) {
        int cnt = (d3hi - d3lo + 1) * 16;
        if (t < cnt) {
            int rr = d3lo + (t >> 4), oj = t & 15;
            int y0 = 8 * rr + 3 - alo, x0 = 8 * oj + 3;
            sD3[(rr - d3lo) * 16 + oj] =
                0.25f * (sA[y0 * 128 + x0] + sA[y0 * 128 + x0 + 1] +
                         sA[(y0 + 1) * 128 + x0] + sA[(y0 + 1) * 128 + x0 + 1]);
        }
    }

    // full-res conv for this strip (reads only sA; relative rows)
    float c0r[2] = {0.f, 0.f};
    if (G0 != 0.f) {
#pragma unroll
        for (int k = 0; k < 2; k++) {
            int p = k * 1024 + t;
            c0r[k] = conv_rel(sA, 128, alo, h0 + (p >> 7), p & 127, k9, bias);
        }
    }

    __syncthreads();  // sD* windows complete

    if (G1 != 0.f) {
        int cnt = (c1hi - c1lo + 1) * 64;
        if (t < cnt) {
            int rr = c1lo + (t >> 6), oj = t & 63;
            sC1[(rr - c1lo) * 64 + oj] = conv_rel(sD1, 64, d1lo, rr, oj, k9, bias);
        }
    }
    if (G2 != 0.f) {
        int cnt = (c2hi - c2lo + 1) * 32;
        if (t < cnt) {
            int rr = c2lo + (t >> 5), oj = t & 31;
            sC2[(rr - c2lo) * 32 + oj] = conv_rel(sD2, 32, d2lo, rr, oj, k9, bias);
        }
    }
    if (G3 != 0.f) {
        int cnt = (c3hi - c3lo + 1) * 16;
        if (t < cnt) {
            int rr = c3lo + (t >> 4), oj = t & 15;
            sC3[(rr - c3lo) * 16 + oj] = conv_rel(sD3, 16, d3lo, rr, oj, k9, bias);
        }
    }

    __syncthreads();  // sC* windows complete

    float* gm = (float*)g_mixed4;
#pragma unroll
    for (int k = 0; k < 2; k++) {
        int p = k * 1024 + t;
        int h = h0 + (p >> 7), w = p & 127;
        float acc = G0 * c0r[k];
        if (G1 != 0.f) acc += G1 * up_rel(sC1, 64, c1lo, h, w, 0.5f);
        if (G2 != 0.f) acc += G2 * up_rel(sC2, 32, c2lo, h, w, 0.25f);
        if (G3 != 0.f) acc += G3 * up_rel(sC3, 16, c3lo, h, w, 0.125f);
        gm[(b * Nn + h * 128 + w) * 4 + r] = acc;
    }
}

// ---------------- kernel 4: out = x + mixed @ Wu + bu ----------------
// 16384 blocks x 384 threads (R11 exact). Thread owns a fixed float4 d-chunk;
// weights in registers. Per 16B of stream: 2 LDG.128 + 1 STG.128.
__global__ void k4_out(const float* __restrict__ x,
                       const float* __restrict__ Wu,
                       const float* __restrict__ bu,
                       float* __restrict__ out) {
    int t = threadIdx.x;
    int sub = t / 192;          // 0..1
    int d4 = t - sub * 192;     // float4 column 0..191

    float4 w0 = __ldg((const float4*)Wu + 0 * 192 + d4);
    float4 w1 = __ldg((const float4*)Wu + 1 * 192 + d4);
    float4 w2 = __ldg((const float4*)Wu + 2 * 192 + d4);
    float4 bb = __ldg((const float4*)bu + d4);

    long rbase = (long)blockIdx.x * 8;
    const float4* xp = (const float4*)x;
    float4* op = (float4*)out;

    pdl_wait();   // k3's g_mixed4 now visible

#pragma unroll
    for (int i = 0; i < 4; i++) {
        long row = rbase + i * 2 + sub;
        float4 m = __ldg(g_mixed4 + row);   // (m0,m1,m2,·)
        long idx = row * 192 + d4;
        float4 xv = __ldg(xp + idx);
        float4 o;
        o.x = xv.x + fmaf(m.x, w0.x, fmaf(m.y, w1.x, fmaf(m.z, w2.x, bb.x)));
        o.y = xv.y + fmaf(m.x, w0.y, fmaf(m.y, w1.y, fmaf(m.z, w2.y, bb.y)));
        o.z = xv.z + fmaf(m.x, w0.z, fmaf(m.y, w1.z, fmaf(m.z, w2.z, bb.z)));
        o.w = xv.w + fmaf(m.x, w0.w, fmaf(m.y, w1.w, fmaf(m.z, w2.w, bb.w)));
        op[idx] = o;
    }
}

// ---------------- launcher ----------------
extern "C" void kernel_launch(void* const* d_in, const int* in_sizes, int n_in,
                              void* d_out, int out_size) {
    const float* x     = (const float*)d_in[0];
    const float* noise = (const float*)d_in[1];
    const float* Wd    = (const float*)d_in[2];
    const float* bd    = (const float*)d_in[3];
    const float* Wu    = (const float*)d_in[4];
    const float* bu    = (const float*)d_in[5];
    const float* Wg    = (const float*)d_in[6];
    const float* Wn    = (const float*)d_in[7];
    const float* dwk   = (const float*)d_in[8];
    const float* dwb   = (const float*)d_in[9];
    float* out = (float*)d_out;

    const int SMEM3 = (5376 + 768 + 640 + 256 + 192 + 96 + 64) * 4;  // 29568 B
    cudaFuncSetAttribute(k3_fused, cudaFuncAttributeMaxDynamicSharedMemorySize, SMEM3);

    k1_proj_down<<<4096, 256>>>(x, Wd, bd);

    cudaLaunchAttribute pdl[1];
    pdl[0].id = cudaLaunchAttributeProgrammaticStreamSerialization;
    pdl[0].val.programmaticStreamSerializationAllowed = 1;

    {
        cudaLaunchConfig_t cfg = {};
        cfg.gridDim = dim3(192);
        cfg.blockDim = dim3(1024);
        cfg.dynamicSmemBytes = SMEM3;
        cfg.stream = 0;
        cfg.attrs = pdl;
        cfg.numAttrs = 1;
        cudaLaunchKernelEx(&cfg, k3_fused, noise, Wg, Wn, dwk, dwb);
    }
    {
        cudaLaunchConfig_t cfg = {};
        cfg.gridDim = dim3(16384);
        cfg.blockDim = dim3(384);
        cfg.stream = 0;
        cfg.attrs = pdl;
        cfg.numAttrs = 1;
        cudaLaunchKernelEx(&cfg, k4_out, x, Wu, bu, out);
    }
}

// round 15
// speedup vs baseline: 1.0765x; 1.0041x over previous
#include <cuda_runtime.h>
#include <math.h>

#define Bb 8
#define Nn 16384
#define Dd 768
#define Rr 3
#define NE 4

// ---------------- device scratch ----------------
__device__ float g_feat[Bb * Rr * Nn];      // xr planar [b][r][h*128+w]
__device__ float g_part[4096 * Rr];         // per-block partials (512 per b)
__device__ float4 g_mixed4[Bb * Nn];        // interleaved (m0,m1,m2,unused)

__device__ __forceinline__ void pdl_wait() {
    asm volatile("griddepcontrol.wait;" ::: "memory");
}

// ---------------- kernel 1: xr = x@Wd + bd (planar) + partial sums ----------------
// 4096 blocks x 256 threads; each warp handles 4 consecutive rows.
__global__ void k1_proj_down(const float* __restrict__ x,
                             const float* __restrict__ Wd,
                             const float* __restrict__ bd) {
    __shared__ float sw0[Dd], sw1[Dd], sw2[Dd];
    __shared__ float wsum[32][3];
    int tid = threadIdx.x;
    for (int i = tid; i < Dd; i += 256) {
        sw0[i] = Wd[i * 3 + 0];
        sw1[i] = Wd[i * 3 + 1];
        sw2[i] = Wd[i * 3 + 2];
    }
    __syncthreads();

    int warp = tid >> 5, lane = tid & 31;
    long row0 = ((long)blockIdx.x * 8 + warp) * 4;
    const float4* xp = (const float4*)(x + row0 * Dd);  // row stride 192 float4

    float a00 = 0.f, a01 = 0.f, a02 = 0.f;
    float a10 = 0.f, a11 = 0.f, a12 = 0.f;
    float a20 = 0.f, a21 = 0.f, a22 = 0.f;
    float a30 = 0.f, a31 = 0.f, a32 = 0.f;
#pragma unroll
    for (int c = 0; c < 6; c++) {
        int d4 = c * 32 + lane;
        float4 w0 = *(const float4*)(sw0 + d4 * 4);
        float4 w1 = *(const float4*)(sw1 + d4 * 4);
        float4 w2 = *(const float4*)(sw2 + d4 * 4);
        float4 x0 = __ldg(xp + 0 * 192 + d4);
        float4 x1 = __ldg(xp + 1 * 192 + d4);
        float4 x2 = __ldg(xp + 2 * 192 + d4);
        float4 x3 = __ldg(xp + 3 * 192 + d4);
        a00 = fmaf(x0.x, w0.x, fmaf(x0.y, w0.y, fmaf(x0.z, w0.z, fmaf(x0.w, w0.w, a00))));
        a01 = fmaf(x0.x, w1.x, fmaf(x0.y, w1.y, fmaf(x0.z, w1.z, fmaf(x0.w, w1.w, a01))));
        a02 = fmaf(x0.x, w2.x, fmaf(x0.y, w2.y, fmaf(x0.z, w2.z, fmaf(x0.w, w2.w, a02))));
        a10 = fmaf(x1.x, w0.x, fmaf(x1.y, w0.y, fmaf(x1.z, w0.z, fmaf(x1.w, w0.w, a10))));
        a11 = fmaf(x1.x, w1.x, fmaf(x1.y, w1.y, fmaf(x1.z, w1.z, fmaf(x1.w, w1.w, a11))));
        a12 = fmaf(x1.x, w2.x, fmaf(x1.y, w2.y, fmaf(x1.z, w2.z, fmaf(x1.w, w2.w, a12))));
        a20 = fmaf(x2.x, w0.x, fmaf(x2.y, w0.y, fmaf(x2.z, w0.z, fmaf(x2.w, w0.w, a20))));
        a21 = fmaf(x2.x, w1.x, fmaf(x2.y, w1.y, fmaf(x2.z, w1.z, fmaf(x2.w, w1.w, a21))));
        a22 = fmaf(x2.x, w2.x, fmaf(x2.y, w2.y, fmaf(x2.z, w2.z, fmaf(x2.w, w2.w, a22))));
        a30 = fmaf(x3.x, w0.x, fmaf(x3.y, w0.y, fmaf(x3.z, w0.z, fmaf(x3.w, w0.w, a30))));
        a31 = fmaf(x3.x, w1.x, fmaf(x3.y, w1.y, fmaf(x3.z, w1.z, fmaf(x3.w, w1.w, a31))));
        a32 = fmaf(x3.x, w2.x, fmaf(x3.y, w2.y, fmaf(x3.z, w2.z, fmaf(x3.w, w2.w, a32))));
    }
#pragma unroll
    for (int off = 16; off > 0; off >>= 1) {
        a00 += __shfl_xor_sync(0xFFFFFFFFu, a00, off);
        a01 += __shfl_xor_sync(0xFFFFFFFFu, a01, off);
        a02 += __shfl_xor_sync(0xFFFFFFFFu, a02, off);
        a10 += __shfl_xor_sync(0xFFFFFFFFu, a10, off);
        a11 += __shfl_xor_sync(0xFFFFFFFFu, a11, off);
        a12 += __shfl_xor_sync(0xFFFFFFFFu, a12, off);
        a20 += __shfl_xor_sync(0xFFFFFFFFu, a20, off);
        a21 += __shfl_xor_sync(0xFFFFFFFFu, a21, off);
        a22 += __shfl_xor_sync(0xFFFFFFFFu, a22, off);
        a30 += __shfl_xor_sync(0xFFFFFFFFu, a30, off);
        a31 += __shfl_xor_sync(0xFFFFFFFFu, a31, off);
        a32 += __shfl_xor_sync(0xFFFFFFFFu, a32, off);
    }
    if (lane == 0) {
        float b0 = bd[0], b1 = bd[1], b2 = bd[2];
        int w4 = warp * 4;
        wsum[w4 + 0][0] = a00 + b0; wsum[w4 + 0][1] = a01 + b1; wsum[w4 + 0][2] = a02 + b2;
        wsum[w4 + 1][0] = a10 + b0; wsum[w4 + 1][1] = a11 + b1; wsum[w4 + 1][2] = a12 + b2;
        wsum[w4 + 2][0] = a20 + b0; wsum[w4 + 2][1] = a21 + b1; wsum[w4 + 2][2] = a22 + b2;
        wsum[w4 + 3][0] = a30 + b0; wsum[w4 + 3][1] = a31 + b1; wsum[w4 + 3][2] = a32 + b2;
    }
    __syncthreads();

    int b = blockIdx.x >> 9;               // 512 blocks per batch
    int nbase = (blockIdx.x & 511) * 32;
    if (tid < 96) {
        int r = tid >> 5, n = tid & 31;
        g_feat[((b * Rr + r) * Nn) + nbase + n] = wsum[n][r];
    }
    if (tid < 3) {
        float acc = 0.f;
#pragma unroll
        for (int n = 0; n < 32; n++) acc += wsum[n][tid];
        g_part[blockIdx.x * Rr + tid] = acc;
    }
}

// ---------------- fused middle: gating + pyramid + conv + mix ----------------
__device__ __forceinline__ float conv3x3s(const float* src, int S,
                                          int oi, int oj,
                                          const float* k9, float bias) {
    float acc = bias;
#pragma unroll
    for (int di = 0; di < 3; di++) {
        int y = oi + di - 1;
        if ((unsigned)y >= (unsigned)S) continue;
#pragma unroll
        for (int dj = 0; dj < 3; dj++) {
            int xx = oj + dj - 1;
            if ((unsigned)xx >= (unsigned)S) continue;
            acc = fmaf(src[y * S + xx], k9[di * 3 + dj], acc);
        }
    }
    return acc;
}

__device__ __forceinline__ float up_sample_s(const float* src, int S,
                                             int h, int w, float ratio) {
    float sy = (h + 0.5f) * ratio - 0.5f;
    float sx = (w + 0.5f) * ratio - 0.5f;
    float fy = floorf(sy), fx = floorf(sx);
    float wy = sy - fy, wx = sx - fx;
    int y0 = (int)fy, x0 = (int)fx;
    int ya = max(y0, 0), yb = min(y0 + 1, S - 1);
    int xa = max(x0, 0), xb = min(x0 + 1, S - 1);
    float v00 = src[ya * S + xa], v01 = src[ya * S + xb];
    float v10 = src[yb * S + xa], v11 = src[yb * S + xb];
    float top = v00 + wx * (v01 - v00);
    float bot = v10 + wx * (v11 - v10);
    return top + wy * (bot - top);
}

// 96 blocks (4 row-strips of 32 per (b,r) plane) x 1024 threads; smem ~106KB.
__global__ void k3_fused(const float* __restrict__ noise,
                         const float* __restrict__ Wg,
                         const float* __restrict__ Wn,
                         const float* __restrict__ dwk,
                         const float* __restrict__ dwb) {
    extern __shared__ float sm[];
    float* sA  = sm;            // 16384 (window-filled)
    float* sD1 = sA + 16384;    // 4096
    float* sC1 = sD1 + 4096;    // 4096
    float* sD2 = sC1 + 4096;    // 1024
    float* sC2 = sD2 + 1024;    // 1024
    float* sD3 = sC2 + 1024;    // 256
    float* sC3 = sD3 + 256;     // 256
    __shared__ float sxa[3];
    __shared__ float sG[NE];

    int ch = blockIdx.x >> 2;
    int strip = blockIdx.x & 3;
    int h0 = strip * 32;
    int b = ch / 3, r = ch % 3;
    int t = threadIdx.x;

    // prologue independent of k1 (runs before wait under PDL)
    float k9[9];
#pragma unroll
    for (int j = 0; j < 9; j++) k9[j] = __ldg(dwk + r * 9 + j);
    float bias = __ldg(dwb + r);

    int alo = max(h0 - 13, 0), ahi = min(h0 + 44, 127);
    int d1lo = max(h0 / 2 - 2, 0), d1hi = min(h0 / 2 + 17, 63);
    int c1lo = max(h0 / 2 - 1, 0), c1hi = min(h0 / 2 + 16, 63);
    int d2lo = max(h0 / 4 - 2, 0), d2hi = min(h0 / 4 + 9, 31);
    int c2lo = max(h0 / 4 - 1, 0), c2hi = min(h0 / 4 + 8, 31);
    int d3lo = max(h0 / 8 - 2, 0), d3hi = min(h0 / 8 + 5, 15);
    int c3lo = max(h0 / 8 - 1, 0), c3hi = min(h0 / 8 + 4, 15);

    pdl_wait();   // k1's g_feat / g_part now visible

    {
        const float4* src = (const float4*)(g_feat + ch * Nn);
        float4* dst = (float4*)sA;
        int cnt4 = (ahi - alo + 1) * 32;
        int base4 = alo * 32;
        for (int i = t; i < cnt4; i += 1024) dst[base4 + i] = __ldg(src + base4 + i);
    }

    if (t < 96) {
        int warp = t >> 5, lane = t & 31;
        float s0 = 0.f, s1 = 0.f, s2 = 0.f, s3 = 0.f;
        const float* pp = g_part + b * 512 * Rr + warp;
#pragma unroll
        for (int i = 0; i < 4; i++) {
            s0 += __ldg(pp + (lane + (i * 4 + 0) * 32) * Rr);
            s1 += __ldg(pp + (lane + (i * 4 + 1) * 32) * Rr);
            s2 += __ldg(pp + (lane + (i * 4 + 2) * 32) * Rr);
            s3 += __ldg(pp + (lane + (i * 4 + 3) * 32) * Rr);
        }
        float s = (s0 + s1) + (s2 + s3);
#pragma unroll
        for (int off = 16; off > 0; off >>= 1)
            s += __shfl_xor_sync(0xFFFFFFFFu, s, off);
        if (lane == 0) sxa[warp] = s * (1.0f / (float)Nn);
    }
    __syncthreads();

    if (t == 0) {
        float xa0 = sxa[0], xa1 = sxa[1], xa2 = sxa[2];
        float Hlog[NE];
#pragma unroll
        for (int e = 0; e < NE; e++) {
            float hg = xa0 * Wg[0 * NE + e] + xa1 * Wg[1 * NE + e] + xa2 * Wg[2 * NE + e];
            float hn = xa0 * Wn[0 * NE + e] + xa1 * Wn[1 * NE + e] + xa2 * Wn[2 * NE + e];
            float sp = fmaxf(hn, 0.f) + log1pf(expf(-fabsf(hn)));
            Hlog[e] = hg + noise[b * NE + e] * sp;
        }
        int i1 = 0;
#pragma unroll
        for (int e = 1; e < NE; e++) if (Hlog[e] > Hlog[i1]) i1 = e;
        int i2 = -1;
#pragma unroll
        for (int e = 0; e < NE; e++) {
            if (e == i1) continue;
            if (i2 < 0 || Hlog[e] > Hlog[i2]) i2 = e;
        }
        float e2 = expf(Hlog[i2] - Hlog[i1]);
        float invZ = 1.0f / (1.0f + e2);
#pragma unroll
        for (int e = 0; e < NE; e++)
            sG[e] = (e == i1) ? invZ : ((e == i2) ? e2 * invZ : 0.0f);
    }

    __syncthreads();  // sA window + gating ready

    float G0 = sG[0], G1 = sG[1], G2 = sG[2], G3 = sG[3];

    if (G1 != 0.f) {
        int cnt = (d1hi - d1lo + 1) * 64;
        for (int i = t; i < cnt; i += 1024) {
            int rr = d1lo + (i >> 6), oj = i & 63;
            int y0 = 2 * rr, x0 = 2 * oj;
            sD1[rr * 64 + oj] = 0.25f * (sA[y0 * 128 + x0] + sA[y0 * 128 + x0 + 1] +
                                         sA[(y0 + 1) * 128 + x0] + sA[(y0 + 1) * 128 + x0 + 1]);
        }
    }
    if (G2 != 0.f) {
        int cnt = (d2hi - d2lo + 1) * 32;
        if (t < cnt) {
            int rr = d2lo + (t >> 5), oj = t & 31;
            int y0 = 4 * rr + 1, x0 = 4 * oj + 1;
            sD2[rr * 32 + oj] = 0.25f * (sA[y0 * 128 + x0] + sA[y0 * 128 + x0 + 1] +
                                         sA[(y0 + 1) * 128 + x0] + sA[(y0 + 1) * 128 + x0 + 1]);
        }
    }
    if (G3 != 0.f) {
        int cnt = (d3hi - d3lo + 1) * 16;
        if (t < cnt) {
            int rr = d3lo + (t >> 4), oj = t & 15;
            int y0 = 8 * rr + 3, x0 = 8 * oj + 3;
            sD3[rr * 16 + oj] = 0.25f * (sA[y0 * 128 + x0] + sA[y0 * 128 + x0 + 1] +
                                         sA[(y0 + 1) * 128 + x0] + sA[(y0 + 1) * 128 + x0 + 1]);
        }
    }

    float c0r[4] = {0.f, 0.f, 0.f, 0.f};
    if (G0 != 0.f) {
#pragma unroll
        for (int k = 0; k < 4; k++) {
            int p = k * 1024 + t;
            c0r[k] = conv3x3s(sA, 128, h0 + (p >> 7), p & 127, k9, bias);
        }
    }

    __syncthreads();  // sD* windows complete

    if (G1 != 0.f) {
        int cnt = (c1hi - c1lo + 1) * 64;
        for (int i = t; i < cnt; i += 1024) {
            int rr = c1lo + (i >> 6), oj = i & 63;
            sC1[rr * 64 + oj] = conv3x3s(sD1, 64, rr, oj, k9, bias);
        }
    }
    if (G2 != 0.f) {
        int cnt = (c2hi - c2lo + 1) * 32;
        if (t < cnt) {
            int rr = c2lo + (t >> 5), oj = t & 31;
            sC2[rr * 32 + oj] = conv3x3s(sD2, 32, rr, oj, k9, bias);
        }
    }
    if (G3 != 0.f) {
        int cnt = (c3hi - c3lo + 1) * 16;
        if (t < cnt) {
            int rr = c3lo + (t >> 4), oj = t & 15;
            sC3[rr * 16 + oj] = conv3x3s(sD3, 16, rr, oj, k9, bias);
        }
    }

    __syncthreads();  // sC* windows complete

    float* gm = (float*)g_mixed4;
#pragma unroll
    for (int k = 0; k < 4; k++) {
        int p = k * 1024 + t;
        int h = h0 + (p >> 7), w = p & 127;
        float acc = G0 * c0r[k];
        if (G1 != 0.f) acc += G1 * up_sample_s(sC1, 64, h, w, 0.5f);
        if (G2 != 0.f) acc += G2 * up_sample_s(sC2, 32, h, w, 0.25f);
        if (G3 != 0.f) acc += G3 * up_sample_s(sC3, 16, h, w, 0.125f);
        gm[(b * Nn + h * 128 + w) * 4 + r] = acc;
    }
}

// ---------------- kernel 4: out = x + mixed @ Wu + bu ----------------
// 16384 blocks x 384 threads. Thread owns a fixed float4 d-chunk; weights in
// registers (loaded before pdl_wait). Per 16B of stream: 2 LDG.128 + 1 STG.128.
__global__ void k4_out(const float* __restrict__ x,
                       const float* __restrict__ Wu,
                       const float* __restrict__ bu,
                       float* __restrict__ out) {
    int t = threadIdx.x;
    int sub = t / 192;          // 0..1
    int d4 = t - sub * 192;     // float4 column 0..191

    float4 w0 = __ldg((const float4*)Wu + 0 * 192 + d4);
    float4 w1 = __ldg((const float4*)Wu + 1 * 192 + d4);
    float4 w2 = __ldg((const float4*)Wu + 2 * 192 + d4);
    float4 bb = __ldg((const float4*)bu + d4);

    long rbase = (long)blockIdx.x * 8;
    const float4* xp = (const float4*)x;
    float4* op = (float4*)out;

    pdl_wait();   // k3's g_mixed4 now visible

#pragma unroll
    for (int i = 0; i < 4; i++) {
        long row = rbase + i * 2 + sub;
        float4 m = __ldg(g_mixed4 + row);   // (m0,m1,m2,·)
        long idx = row * 192 + d4;
        float4 xv = __ldg(xp + idx);
        float4 o;
        o.x = xv.x + fmaf(m.x, w0.x, fmaf(m.y, w1.x, fmaf(m.z, w2.x, bb.x)));
        o.y = xv.y + fmaf(m.x, w0.y, fmaf(m.y, w1.y, fmaf(m.z, w2.y, bb.y)));
        o.z = xv.z + fmaf(m.x, w0.z, fmaf(m.y, w1.z, fmaf(m.z, w2.z, bb.z)));
        o.w = xv.w + fmaf(m.x, w0.w, fmaf(m.y, w1.w, fmaf(m.z, w2.w, bb.w)));
        op[idx] = o;
    }
}

// ---------------- launcher ----------------
extern "C" void kernel_launch(void* const* d_in, const int* in_sizes, int n_in,
                              void* d_out, int out_size) {
    const float* x     = (const float*)d_in[0];
    const float* noise = (const float*)d_in[1];
    const float* Wd    = (const float*)d_in[2];
    const float* bd    = (const float*)d_in[3];
    const float* Wu    = (const float*)d_in[4];
    const float* bu    = (const float*)d_in[5];
    const float* Wg    = (const float*)d_in[6];
    const float* Wn    = (const float*)d_in[7];
    const float* dwk   = (const float*)d_in[8];
    const float* dwb   = (const float*)d_in[9];
    float* out = (float*)d_out;

    const int SMEM3 = (16384 + 4096 * 2 + 1024 * 2 + 256 * 2) * 4;
    cudaFuncSetAttribute(k3_fused, cudaFuncAttributeMaxDynamicSharedMemorySize, SMEM3);

    k1_proj_down<<<4096, 256>>>(x, Wd, bd);

    cudaLaunchAttribute pdl[1];
    pdl[0].id = cudaLaunchAttributeProgrammaticStreamSerialization;
    pdl[0].val.programmaticStreamSerializationAllowed = 1;

    {
        cudaLaunchConfig_t cfg = {};
        cfg.gridDim = dim3(96);
        cfg.blockDim = dim3(1024);
        cfg.dynamicSmemBytes = SMEM3;
        cfg.stream = 0;
        cfg.attrs = pdl;
        cfg.numAttrs = 1;
        cudaLaunchKernelEx(&cfg, k3_fused, noise, Wg, Wn, dwk, dwb);
    }
    {
        cudaLaunchConfig_t cfg = {};
        cfg.gridDim = dim3(16384);
        cfg.blockDim = dim3(384);
        cfg.stream = 0;
        cfg.attrs = pdl;
        cfg.numAttrs = 1;
        cudaLaunchKernelEx(&cfg, k4_out, x, Wu, bu, out);
    }
}

// round 16
// speedup vs baseline: 1.0783x; 1.0017x over previous
#include <cuda_runtime.h>
#include <math.h>

#define Bb 8
#define Nn 16384
#define Dd 768
#define Rr 3
#define NE 4

// ---------------- device scratch ----------------
__device__ float g_feat[Bb * Rr * Nn];      // xr planar [b][r][h*128+w]
__device__ float g_part[4096 * Rr];         // per-block partials (512 per b)
__device__ float4 g_mixed4[Bb * Nn];        // interleaved (m0,m1,m2,unused)

__device__ __forceinline__ void pdl_wait() {
    asm volatile("griddepcontrol.wait;" ::: "memory");
}

// ---------------- kernel 1: xr = x@Wd + bd (planar) + partial sums ----------------
// 4096 blocks x 256 threads; each warp handles 4 consecutive rows.
// Launched with PDL: loads/compute overlap the previous kernel's drain; the
// griddepcontrol.wait before the g_feat/g_part stores keeps ordering vs the
// previous replay's k3 reads.
__global__ void k1_proj_down(const float* __restrict__ x,
                             const float* __restrict__ Wd,
                             const float* __restrict__ bd) {
    __shared__ float sw0[Dd], sw1[Dd], sw2[Dd];
    __shared__ float wsum[32][3];
    int tid = threadIdx.x;
    for (int i = tid; i < Dd; i += 256) {
        sw0[i] = Wd[i * 3 + 0];
        sw1[i] = Wd[i * 3 + 1];
        sw2[i] = Wd[i * 3 + 2];
    }
    __syncthreads();

    int warp = tid >> 5, lane = tid & 31;
    long row0 = ((long)blockIdx.x * 8 + warp) * 4;
    const float4* xp = (const float4*)(x + row0 * Dd);  // row stride 192 float4

    float a00 = 0.f, a01 = 0.f, a02 = 0.f;
    float a10 = 0.f, a11 = 0.f, a12 = 0.f;
    float a20 = 0.f, a21 = 0.f, a22 = 0.f;
    float a30 = 0.f, a31 = 0.f, a32 = 0.f;
#pragma unroll
    for (int c = 0; c < 6; c++) {
        int d4 = c * 32 + lane;
        float4 w0 = *(const float4*)(sw0 + d4 * 4);
        float4 w1 = *(const float4*)(sw1 + d4 * 4);
        float4 w2 = *(const float4*)(sw2 + d4 * 4);
        float4 x0 = __ldg(xp + 0 * 192 + d4);
        float4 x1 = __ldg(xp + 1 * 192 + d4);
        float4 x2 = __ldg(xp + 2 * 192 + d4);
        float4 x3 = __ldg(xp + 3 * 192 + d4);
        a00 = fmaf(x0.x, w0.x, fmaf(x0.y, w0.y, fmaf(x0.z, w0.z, fmaf(x0.w, w0.w, a00))));
        a01 = fmaf(x0.x, w1.x, fmaf(x0.y, w1.y, fmaf(x0.z, w1.z, fmaf(x0.w, w1.w, a01))));
        a02 = fmaf(x0.x, w2.x, fmaf(x0.y, w2.y, fmaf(x0.z, w2.z, fmaf(x0.w, w2.w, a02))));
        a10 = fmaf(x1.x, w0.x, fmaf(x1.y, w0.y, fmaf(x1.z, w0.z, fmaf(x1.w, w0.w, a10))));
        a11 = fmaf(x1.x, w1.x, fmaf(x1.y, w1.y, fmaf(x1.z, w1.z, fmaf(x1.w, w1.w, a11))));
        a12 = fmaf(x1.x, w2.x, fmaf(x1.y, w2.y, fmaf(x1.z, w2.z, fmaf(x1.w, w2.w, a12))));
        a20 = fmaf(x2.x, w0.x, fmaf(x2.y, w0.y, fmaf(x2.z, w0.z, fmaf(x2.w, w0.w, a20))));
        a21 = fmaf(x2.x, w1.x, fmaf(x2.y, w1.y, fmaf(x2.z, w1.z, fmaf(x2.w, w1.w, a21))));
        a22 = fmaf(x2.x, w2.x, fmaf(x2.y, w2.y, fmaf(x2.z, w2.z, fmaf(x2.w, w2.w, a22))));
        a30 = fmaf(x3.x, w0.x, fmaf(x3.y, w0.y, fmaf(x3.z, w0.z, fmaf(x3.w, w0.w, a30))));
        a31 = fmaf(x3.x, w1.x, fmaf(x3.y, w1.y, fmaf(x3.z, w1.z, fmaf(x3.w, w1.w, a31))));
        a32 = fmaf(x3.x, w2.x, fmaf(x3.y, w2.y, fmaf(x3.z, w2.z, fmaf(x3.w, w2.w, a32))));
    }
#pragma unroll
    for (int off = 16; off > 0; off >>= 1) {
        a00 += __shfl_xor_sync(0xFFFFFFFFu, a00, off);
        a01 += __shfl_xor_sync(0xFFFFFFFFu, a01, off);
        a02 += __shfl_xor_sync(0xFFFFFFFFu, a02, off);
        a10 += __shfl_xor_sync(0xFFFFFFFFu, a10, off);
        a11 += __shfl_xor_sync(0xFFFFFFFFu, a11, off);
        a12 += __shfl_xor_sync(0xFFFFFFFFu, a12, off);
        a20 += __shfl_xor_sync(0xFFFFFFFFu, a20, off);
        a21 += __shfl_xor_sync(0xFFFFFFFFu, a21, off);
        a22 += __shfl_xor_sync(0xFFFFFFFFu, a22, off);
        a30 += __shfl_xor_sync(0xFFFFFFFFu, a30, off);
        a31 += __shfl_xor_sync(0xFFFFFFFFu, a31, off);
        a32 += __shfl_xor_sync(0xFFFFFFFFu, a32, off);
    }
    if (lane == 0) {
        float b0 = bd[0], b1 = bd[1], b2 = bd[2];
        int w4 = warp * 4;
        wsum[w4 + 0][0] = a00 + b0; wsum[w4 + 0][1] = a01 + b1; wsum[w4 + 0][2] = a02 + b2;
        wsum[w4 + 1][0] = a10 + b0; wsum[w4 + 1][1] = a11 + b1; wsum[w4 + 1][2] = a12 + b2;
        wsum[w4 + 2][0] = a20 + b0; wsum[w4 + 2][1] = a21 + b1; wsum[w4 + 2][2] = a22 + b2;
        wsum[w4 + 3][0] = a30 + b0; wsum[w4 + 3][1] = a31 + b1; wsum[w4 + 3][2] = a32 + b2;
    }
    __syncthreads();

    pdl_wait();   // order our scratch stores after previous replay's consumers

    int b = blockIdx.x >> 9;               // 512 blocks per batch
    int nbase = (blockIdx.x & 511) * 32;
    if (tid < 96) {
        int r = tid >> 5, n = tid & 31;
        g_feat[((b * Rr + r) * Nn) + nbase + n] = wsum[n][r];
    }
    if (tid < 3) {
        float acc = 0.f;
#pragma unroll
        for (int n = 0; n < 32; n++) acc += wsum[n][tid];
        g_part[blockIdx.x * Rr + tid] = acc;
    }
}

// ---------------- fused middle: gating + pyramid + conv + mix ----------------
__device__ __forceinline__ float conv3x3s(const float* src, int S,
                                          int oi, int oj,
                                          const float* k9, float bias) {
    float acc = bias;
#pragma unroll
    for (int di = 0; di < 3; di++) {
        int y = oi + di - 1;
        if ((unsigned)y >= (unsigned)S) continue;
#pragma unroll
        for (int dj = 0; dj < 3; dj++) {
            int xx = oj + dj - 1;
            if ((unsigned)xx >= (unsigned)S) continue;
            acc = fmaf(src[y * S + xx], k9[di * 3 + dj], acc);
        }
    }
    return acc;
}

__device__ __forceinline__ float up_sample_s(const float* src, int S,
                                             int h, int w, float ratio) {
    float sy = (h + 0.5f) * ratio - 0.5f;
    float sx = (w + 0.5f) * ratio - 0.5f;
    float fy = floorf(sy), fx = floorf(sx);
    float wy = sy - fy, wx = sx - fx;
    int y0 = (int)fy, x0 = (int)fx;
    int ya = max(y0, 0), yb = min(y0 + 1, S - 1);
    int xa = max(x0, 0), xb = min(x0 + 1, S - 1);
    float v00 = src[ya * S + xa], v01 = src[ya * S + xb];
    float v10 = src[yb * S + xa], v11 = src[yb * S + xb];
    float top = v00 + wx * (v01 - v00);
    float bot = v10 + wx * (v11 - v10);
    return top + wy * (bot - top);
}

// 96 blocks (4 row-strips of 32 per (b,r) plane) x 1024 threads; smem ~106KB.
__global__ void k3_fused(const float* __restrict__ noise,
                         const float* __restrict__ Wg,
                         const float* __restrict__ Wn,
                         const float* __restrict__ dwk,
                         const float* __restrict__ dwb) {
    extern __shared__ float sm[];
    float* sA  = sm;            // 16384 (window-filled)
    float* sD1 = sA + 16384;    // 4096
    float* sC1 = sD1 + 4096;    // 4096
    float* sD2 = sC1 + 4096;    // 1024
    float* sC2 = sD2 + 1024;    // 1024
    float* sD3 = sC2 + 1024;    // 256
    float* sC3 = sD3 + 256;     // 256
    __shared__ float sxa[3];
    __shared__ float sG[NE];

    int ch = blockIdx.x >> 2;
    int strip = blockIdx.x & 3;
    int h0 = strip * 32;
    int b = ch / 3, r = ch % 3;
    int t = threadIdx.x;

    // prologue independent of k1 (runs before wait under PDL)
    float k9[9];
#pragma unroll
    for (int j = 0; j < 9; j++) k9[j] = __ldg(dwk + r * 9 + j);
    float bias = __ldg(dwb + r);

    int alo = max(h0 - 13, 0), ahi = min(h0 + 44, 127);
    int d1lo = max(h0 / 2 - 2, 0), d1hi = min(h0 / 2 + 17, 63);
    int c1lo = max(h0 / 2 - 1, 0), c1hi = min(h0 / 2 + 16, 63);
    int d2lo = max(h0 / 4 - 2, 0), d2hi = min(h0 / 4 + 9, 31);
    int c2lo = max(h0 / 4 - 1, 0), c2hi = min(h0 / 4 + 8, 31);
    int d3lo = max(h0 / 8 - 2, 0), d3hi = min(h0 / 8 + 5, 15);
    int c3lo = max(h0 / 8 - 1, 0), c3hi = min(h0 / 8 + 4, 15);

    pdl_wait();   // k1's g_feat / g_part now visible

    {
        const float4* src = (const float4*)(g_feat + ch * Nn);
        float4* dst = (float4*)sA;
        int cnt4 = (ahi - alo + 1) * 32;
        int base4 = alo * 32;
        for (int i = t; i < cnt4; i += 1024) dst[base4 + i] = __ldg(src + base4 + i);
    }

    if (t < 96) {
        int warp = t >> 5, lane = t & 31;
        float s0 = 0.f, s1 = 0.f, s2 = 0.f, s3 = 0.f;
        const float* pp = g_part + b * 512 * Rr + warp;
#pragma unroll
        for (int i = 0; i < 4; i++) {
            s0 += __ldg(pp + (lane + (i * 4 + 0) * 32) * Rr);
            s1 += __ldg(pp + (lane + (i * 4 + 1) * 32) * Rr);
            s2 += __ldg(pp + (lane + (i * 4 + 2) * 32) * Rr);
            s3 += __ldg(pp + (lane + (i * 4 + 3) * 32) * Rr);
        }
        float s = (s0 + s1) + (s2 + s3);
#pragma unroll
        for (int off = 16; off > 0; off >>= 1)
            s += __shfl_xor_sync(0xFFFFFFFFu, s, off);
        if (lane == 0) sxa[warp] = s * (1.0f / (float)Nn);
    }
    __syncthreads();

    if (t == 0) {
        float xa0 = sxa[0], xa1 = sxa[1], xa2 = sxa[2];
        float Hlog[NE];
#pragma unroll
        for (int e = 0; e < NE; e++) {
            float hg = xa0 * Wg[0 * NE + e] + xa1 * Wg[1 * NE + e] + xa2 * Wg[2 * NE + e];
            float hn = xa0 * Wn[0 * NE + e] + xa1 * Wn[1 * NE + e] + xa2 * Wn[2 * NE + e];
            float sp = fmaxf(hn, 0.f) + log1pf(expf(-fabsf(hn)));
            Hlog[e] = hg + noise[b * NE + e] * sp;
        }
        int i1 = 0;
#pragma unroll
        for (int e = 1; e < NE; e++) if (Hlog[e] > Hlog[i1]) i1 = e;
        int i2 = -1;
#pragma unroll
        for (int e = 0; e < NE; e++) {
            if (e == i1) continue;
            if (i2 < 0 || Hlog[e] > Hlog[i2]) i2 = e;
        }
        float e2 = expf(Hlog[i2] - Hlog[i1]);
        float invZ = 1.0f / (1.0f + e2);
#pragma unroll
        for (int e = 0; e < NE; e++)
            sG[e] = (e == i1) ? invZ : ((e == i2) ? e2 * invZ : 0.0f);
    }

    __syncthreads();  // sA window + gating ready

    float G0 = sG[0], G1 = sG[1], G2 = sG[2], G3 = sG[3];

    if (G1 != 0.f) {
        int cnt = (d1hi - d1lo + 1) * 64;
        for (int i = t; i < cnt; i += 1024) {
            int rr = d1lo + (i >> 6), oj = i & 63;
            int y0 = 2 * rr, x0 = 2 * oj;
            sD1[rr * 64 + oj] = 0.25f * (sA[y0 * 128 + x0] + sA[y0 * 128 + x0 + 1] +
                                         sA[(y0 + 1) * 128 + x0] + sA[(y0 + 1) * 128 + x0 + 1]);
        }
    }
    if (G2 != 0.f) {
        int cnt = (d2hi - d2lo + 1) * 32;
        if (t < cnt) {
            int rr = d2lo + (t >> 5), oj = t & 31;
            int y0 = 4 * rr + 1, x0 = 4 * oj + 1;
            sD2[rr * 32 + oj] = 0.25f * (sA[y0 * 128 + x0] + sA[y0 * 128 + x0 + 1] +
                                         sA[(y0 + 1) * 128 + x0] + sA[(y0 + 1) * 128 + x0 + 1]);
        }
    }
    if (G3 != 0.f) {
        int cnt = (d3hi - d3lo + 1) * 16;
        if (t < cnt) {
            int rr = d3lo + (t >> 4), oj = t & 15;
            int y0 = 8 * rr + 3, x0 = 8 * oj + 3;
            sD3[rr * 16 + oj] = 0.25f * (sA[y0 * 128 + x0] + sA[y0 * 128 + x0 + 1] +
                                         sA[(y0 + 1) * 128 + x0] + sA[(y0 + 1) * 128 + x0 + 1]);
        }
    }

    float c0r[4] = {0.f, 0.f, 0.f, 0.f};
    if (G0 != 0.f) {
#pragma unroll
        for (int k = 0; k < 4; k++) {
            int p = k * 1024 + t;
            c0r[k] = conv3x3s(sA, 128, h0 + (p >> 7), p & 127, k9, bias);
        }
    }

    __syncthreads();  // sD* windows complete

    if (G1 != 0.f) {
        int cnt = (c1hi - c1lo + 1) * 64;
        for (int i = t; i < cnt; i += 1024) {
            int rr = c1lo + (i >> 6), oj = i & 63;
            sC1[rr * 64 + oj] = conv3x3s(sD1, 64, rr, oj, k9, bias);
        }
    }
    if (G2 != 0.f) {
        int cnt = (c2hi - c2lo + 1) * 32;
        if (t < cnt) {
            int rr = c2lo + (t >> 5), oj = t & 31;
            sC2[rr * 32 + oj] = conv3x3s(sD2, 32, rr, oj, k9, bias);
        }
    }
    if (G3 != 0.f) {
        int cnt = (c3hi - c3lo + 1) * 16;
        if (t < cnt) {
            int rr = c3lo + (t >> 4), oj = t & 15;
            sC3[rr * 16 + oj] = conv3x3s(sD3, 16, rr, oj, k9, bias);
        }
    }

    __syncthreads();  // sC* windows complete

    float* gm = (float*)g_mixed4;
#pragma unroll
    for (int k = 0; k < 4; k++) {
        int p = k * 1024 + t;
        int h = h0 + (p >> 7), w = p & 127;
        float acc = G0 * c0r[k];
        if (G1 != 0.f) acc += G1 * up_sample_s(sC1, 64, h, w, 0.5f);
        if (G2 != 0.f) acc += G2 * up_sample_s(sC2, 32, h, w, 0.25f);
        if (G3 != 0.f) acc += G3 * up_sample_s(sC3, 16, h, w, 0.125f);
        gm[(b * Nn + h * 128 + w) * 4 + r] = acc;
    }
}

// ---------------- kernel 4: out = x + mixed @ Wu + bu ----------------
// 16384 blocks x 384 threads. Thread owns a fixed float4 d-chunk; weights in
// registers (loaded before pdl_wait). Per 16B of stream: 2 LDG.128 + 1 STG.128.
__global__ void k4_out(const float* __restrict__ x,
                       const float* __restrict__ Wu,
                       const float* __restrict__ bu,
                       float* __restrict__ out) {
    int t = threadIdx.x;
    int sub = t / 192;          // 0..1
    int d4 = t - sub * 192;     // float4 column 0..191

    float4 w0 = __ldg((const float4*)Wu + 0 * 192 + d4);
    float4 w1 = __ldg((const float4*)Wu + 1 * 192 + d4);
    float4 w2 = __ldg((const float4*)Wu + 2 * 192 + d4);
    float4 bb = __ldg((const float4*)bu + d4);

    long rbase = (long)blockIdx.x * 8;
    const float4* xp = (const float4*)x;
    float4* op = (float4*)out;

    pdl_wait();   // k3's g_mixed4 now visible

#pragma unroll
    for (int i = 0; i < 4; i++) {
        long row = rbase + i * 2 + sub;
        float4 m = __ldg(g_mixed4 + row);   // (m0,m1,m2,·)
        long idx = row * 192 + d4;
        float4 xv = __ldg(xp + idx);
        float4 o;
        o.x = xv.x + fmaf(m.x, w0.x, fmaf(m.y, w1.x, fmaf(m.z, w2.x, bb.x)));
        o.y = xv.y + fmaf(m.x, w0.y, fmaf(m.y, w1.y, fmaf(m.z, w2.y, bb.y)));
        o.z = xv.z + fmaf(m.x, w0.z, fmaf(m.y, w1.z, fmaf(m.z, w2.z, bb.z)));
        o.w = xv.w + fmaf(m.x, w0.w, fmaf(m.y, w1.w, fmaf(m.z, w2.w, bb.w)));
        op[idx] = o;
    }
}

// ---------------- launcher ----------------
extern "C" void kernel_launch(void* const* d_in, const int* in_sizes, int n_in,
                              void* d_out, int out_size) {
    const float* x     = (const float*)d_in[0];
    const float* noise = (const float*)d_in[1];
    const float* Wd    = (const float*)d_in[2];
    const float* bd    = (const float*)d_in[3];
    const float* Wu    = (const float*)d_in[4];
    const float* bu    = (const float*)d_in[5];
    const float* Wg    = (const float*)d_in[6];
    const float* Wn    = (const float*)d_in[7];
    const float* dwk   = (const float*)d_in[8];
    const float* dwb   = (const float*)d_in[9];
    float* out = (float*)d_out;

    const int SMEM3 = (16384 + 4096 * 2 + 1024 * 2 + 256 * 2) * 4;
    cudaFuncSetAttribute(k3_fused, cudaFuncAttributeMaxDynamicSharedMemorySize, SMEM3);

    cudaLaunchAttribute pdl[1];
    pdl[0].id = cudaLaunchAttributeProgrammaticStreamSerialization;
    pdl[0].val.programmaticStreamSerializationAllowed = 1;

    {
        cudaLaunchConfig_t cfg = {};
        cfg.gridDim = dim3(4096);
        cfg.blockDim = dim3(256);
        cfg.stream = 0;
        cfg.attrs = pdl;
        cfg.numAttrs = 1;
        cudaLaunchKernelEx(&cfg, k1_proj_down, x, Wd, bd);
    }
    {
        cudaLaunchConfig_t cfg = {};
        cfg.gridDim = dim3(96);
        cfg.blockDim = dim3(1024);
        cfg.dynamicSmemBytes = SMEM3;
        cfg.stream = 0;
        cfg.attrs = pdl;
        cfg.numAttrs = 1;
        cudaLaunchKernelEx(&cfg, k3_fused, noise, Wg, Wn, dwk, dwb);
    }
    {
        cudaLaunchConfig_t cfg = {};
        cfg.gridDim = dim3(16384);
        cfg.blockDim = dim3(384);
        cfg.stream = 0;
        cfg.attrs = pdl;
        cfg.numAttrs = 1;
        cudaLaunchKernelEx(&cfg, k4_out, x, Wu, bu, out);
    }
}